// round 16
// baseline (speedup 1.0000x reference)
#include <cuda_runtime.h>
#include <cuda_bf16.h>
#include <math.h>
#include <stdint.h>

// ---------------- problem constants ----------------
#define Bx      16
#define Lx      64
#define Nx      1024
#define HAND    99
#define Jx      21
#define HIDD    512
#define NLAYERS 4
#define NHEADS  8
#define DHD     64
#define CATD    2273
#define SEQ     128
#define M1      (Bx*Lx)      // 1024
#define M2      (Bx*SEQ)     // 2048
#define KWFC    1152         // padded word-K for fc
#define KWH     256          // HIDD/2
#define KWF     1024         // 4*HIDD/2

// ---------------- scratch arena (words = 4B each) ----------------
#define OFF_PCT   0
#define SZ_PCT    (M1*Nx*3)
#define OFF_PCN   (OFF_PCT + SZ_PCT)
#define SZ_PCN    (M1*Nx)
#define OFF_ATT   (OFF_PCN + SZ_PCN)
#define SZ_ATT    (2*M1*Jx*3)
#define OFF_CATH  (OFF_ATT + SZ_ATT)
#define SZ_CATH   (2*M1*KWFC)
#define OFF_CATL  (OFF_CATH + SZ_CATH)
#define SZ_CATL   SZ_CATH
#define OFF_FC    (OFF_CATL + SZ_CATL)
#define SZ_FC     (2 * 2*M1*HIDD)
#define OFF_X     (OFF_FC + SZ_FC)
#define SZ_X      (M2*HIDD)
#define OFF_XH    (OFF_X + SZ_X)
#define SZ_XH     (M2*KWH)
#define OFF_XL    (OFF_XH + SZ_XH)
#define SZ_XL     SZ_XH
#define OFF_H     (OFF_XL + SZ_XL)
#define SZ_H      (M2*HIDD)
#define OFF_HH    (OFF_H + SZ_H)
#define SZ_HH     (M2*KWH)
#define OFF_HL    (OFF_HH + SZ_HH)
#define SZ_HL     SZ_HH
#define OFF_QKV   (OFF_HL + SZ_HL)
#define SZ_QKV    (M2*3*HIDD)
#define OFF_AOH   (OFF_QKV + SZ_QKV)
#define SZ_AOH    (M2*KWH)
#define OFF_AOL   (OFF_AOH + SZ_AOH)
#define SZ_AOL    SZ_AOH
#define OFF_FFH   (OFF_AOL + SZ_AOL)
#define SZ_FFH    (M2*KWF)
#define OFF_FFL   (OFF_FFH + SZ_FFH)
#define SZ_FFL    SZ_FFH
#define OFF_TMP   (OFF_FFL + SZ_FFL)
#define SZ_TMP    (2 * M2*HIDD)
// packed weights (group layout: word idx = (kwg*Npad + n)*4 + j)
#define OFF_FCWH  (OFF_TMP + SZ_TMP)
#define SZ_FCWH   (2*KWFC*HIDD)
#define OFF_FCWL  (OFF_FCWH + SZ_FCWH)
#define SZ_FCWL   SZ_FCWH
#define OFF_QWH   (OFF_FCWL + SZ_FCWL)
#define SZ_QWH    (NLAYERS*KWH*3*HIDD)
#define OFF_QWL   (OFF_QWH + SZ_QWH)
#define SZ_QWL    SZ_QWH
#define OFF_OWH   (OFF_QWL + SZ_QWL)
#define SZ_OWH    (NLAYERS*KWH*HIDD)
#define OFF_OWL   (OFF_OWH + SZ_OWH)
#define SZ_OWL    SZ_OWH
#define OFF_W1H   (OFF_OWL + SZ_OWL)
#define SZ_W1H    (NLAYERS*KWH*4*HIDD)
#define OFF_W1L   (OFF_W1H + SZ_W1H)
#define SZ_W1L    SZ_W1H
#define OFF_W2H   (OFF_W1L + SZ_W1L)
#define SZ_W2H    (NLAYERS*KWF*HIDD)
#define OFF_W2L   (OFF_W2H + SZ_W2H)
#define SZ_W2L    SZ_W2H
#define OFF_OUTWH (OFF_W2L + SZ_W2L)
#define SZ_OUTWH  (2*KWH*128)
#define OFF_OUTWL (OFF_OUTWH + SZ_OUTWH)
#define SZ_OUTWL  SZ_OUTWH
#define OFF_PE    (OFF_OUTWL + SZ_OUTWL)
#define SZ_PE     (SEQ*HIDD)
#define SCRATCH_TOTAL (OFF_PE + SZ_PE)

__device__ float g_scratch[SCRATCH_TOTAL];

// ---------------- bf16 helpers ----------------
__device__ __forceinline__ uint32_t pack_bf16(float e, float o) {
    uint32_t r;
    asm("cvt.rn.bf16x2.f32 %0, %1, %2;" : "=r"(r) : "f"(o), "f"(e));
    return r;
}
__device__ __forceinline__ float2 unpack_bf16(uint32_t w) {
    float2 f;
    f.x = __uint_as_float(w << 16);
    f.y = __uint_as_float(w & 0xffff0000u);
    return f;
}
__device__ __forceinline__ void split_pair(float e, float o, uint32_t& hw, uint32_t& lw) {
    hw = pack_bf16(e, o);
    float2 hf = unpack_bf16(hw);
    lw = pack_bf16(e - hf.x, o - hf.y);
}
__device__ __forceinline__ void mma_bf16(float* c, const uint32_t* a, const uint32_t* b) {
    asm("mma.sync.aligned.m16n8k16.row.col.f32.bf16.bf16.f32 "
        "{%0,%1,%2,%3}, {%4,%5,%6,%7}, {%8,%9}, {%0,%1,%2,%3};\n"
        : "+f"(c[0]), "+f"(c[1]), "+f"(c[2]), "+f"(c[3])
        : "r"(a[0]), "r"(a[1]), "r"(a[2]), "r"(a[3]), "r"(b[0]), "r"(b[1]));
}
__device__ __forceinline__ void ldsm_x4(uint32_t* r, uint32_t addr) {
    asm volatile("ldmatrix.sync.aligned.m8n8.x4.shared.b16 {%0,%1,%2,%3}, [%4];"
        : "=r"(r[0]), "=r"(r[1]), "=r"(r[2]), "=r"(r[3]) : "r"(addr));
}
__device__ __forceinline__ uint32_t smem_u32(const void* p) {
    uint32_t a;
    asm("{ .reg .u64 t; cvta.to.shared.u64 t, %1; cvt.u32.u64 %0, t; }" : "=r"(a) : "l"(p));
    return a;
}

// ---------------- weight pre-split: W[K][Nsrc] -> group layout [kwg][Npad][4] ----------------
__global__ void split_w(const float* __restrict__ W, uint32_t* __restrict__ Wh,
                        uint32_t* __restrict__ Wl, int K, int Nsrc, int Npad,
                        size_t wstride, size_t pstride) {
    int n = blockIdx.x * blockDim.x + threadIdx.x;
    if (n >= Npad) return;
    int kwg = blockIdx.y;
    int l   = blockIdx.z;
    const float* Ws = W + (size_t)l * wstride;
    uint32_t hw[4], lw[4];
    #pragma unroll
    for (int j = 0; j < 4; j++) {
        int kw = kwg*4 + j;
        float e = 0.f, o = 0.f;
        if (n < Nsrc) {
            if (2*kw     < K) e = Ws[(size_t)(2*kw)*Nsrc + n];
            if (2*kw + 1 < K) o = Ws[(size_t)(2*kw+1)*Nsrc + n];
        }
        split_pair(e, o, hw[j], lw[j]);
    }
    size_t base = (size_t)l*pstride + ((size_t)kwg*Npad + n)*4;
    *(uint4*)(Wh + base) = make_uint4(hw[0], hw[1], hw[2], hw[3]);
    *(uint4*)(Wl + base) = make_uint4(lw[0], lw[1], lw[2], lw[3]);
}

// ---------------- PE table ----------------
__global__ void pe_table(float* __restrict__ pe) {
    int idx = blockIdx.x * blockDim.x + threadIdx.x;
    if (idx >= SEQ*HIDD) return;
    int d = idx & (HIDD - 1);
    int s = idx >> 9;
    int l = s >> 1, h = s & 1;
    float div = expf((float)(d & ~1) * (-9.2103403719761836f / 512.f));
    float pl = (d & 1) ? cosf((float)l * div) : sinf((float)l * div);
    float pa = (d & 1) ? cosf((float)h * div) : sinf((float)h * div);
    pe[idx] = pl + pa;
}

// ---------------- rot6d + pc transform + norm ----------------
__global__ void transform_kernel(const float* __restrict__ x_obj,
                                 const float* __restrict__ pc,
                                 float* __restrict__ pct,
                                 float* __restrict__ pcn) {
    int bl = blockIdx.x;
    int b  = bl / Lx;
    const float* xo = x_obj + (size_t)bl * 10;
    float tx = xo[0], ty = xo[1], tz = xo[2];
    float a1x = xo[3], a1y = xo[4], a1z = xo[5];
    float a2x = xo[6], a2y = xo[7], a2z = xo[8];
    float n1 = sqrtf(a1x*a1x + a1y*a1y + a1z*a1z);
    float b1x = a1x/n1, b1y = a1y/n1, b1z = a1z/n1;
    float dd  = b1x*a2x + b1y*a2y + b1z*a2z;
    float b2x = a2x - dd*b1x, b2y = a2y - dd*b1y, b2z = a2z - dd*b1z;
    float n2 = sqrtf(b2x*b2x + b2y*b2y + b2z*b2z);
    b2x /= n2; b2y /= n2; b2z /= n2;
    float b3x = b1y*b2z - b1z*b2y;
    float b3y = b1z*b2x - b1x*b2z;
    float b3z = b1x*b2y - b1y*b2x;
    const float* pcb = pc + (size_t)b * Nx * 3;
    for (int n = threadIdx.x; n < Nx; n += blockDim.x) {
        float px = pcb[n*3+0], py = pcb[n*3+1], pz = pcb[n*3+2];
        float ox = b1x*px + b2x*py + b3x*pz + tx;
        float oy = b1y*px + b2y*py + b3y*pz + ty;
        float oz = b1z*px + b2z*py + b3z*pz + tz;
        float* o = pct + ((size_t)bl * Nx + n) * 3;
        o[0] = ox; o[1] = oy; o[2] = oz;
        pcn[(size_t)bl * Nx + n] = sqrtf(ox*ox + oy*oy + oz*oz);
    }
}

// ---------------- nearest-point attention map ----------------
__global__ void attmap_kernel(const float* __restrict__ jl,
                              const float* __restrict__ jr,
                              const float* __restrict__ pct,
                              float* __restrict__ att) {
    __shared__ float pcs[Nx*3];
    int bl = blockIdx.x, hand = blockIdx.y;
    const float* src = pct + (size_t)bl * Nx * 3;
    for (int i = threadIdx.x; i < Nx*3; i += blockDim.x) pcs[i] = src[i];
    __syncthreads();
    int w = threadIdx.x >> 5, lane = threadIdx.x & 31;
    if (w >= Jx) return;
    const float* jp = (hand ? jr : jl) + ((size_t)bl * Jx + w) * 3;
    float jx = jp[0], jy = jp[1], jz = jp[2];
    float jj = jx*jx + jy*jy + jz*jz;
    float best = 3.4e38f; int bidx = Nx;
    for (int n = lane; n < Nx; n += 32) {
        float px = pcs[n*3+0], py = pcs[n*3+1], pz = pcs[n*3+2];
        float pp = px*px + py*py + pz*pz;
        float d2 = jj + pp - 2.f*(jx*px + jy*py + jz*pz);
        if (d2 < best || (d2 == best && n < bidx)) { best = d2; bidx = n; }
    }
    for (int o = 16; o; o >>= 1) {
        float ob = __shfl_down_sync(0xffffffffu, best, o);
        int   oi = __shfl_down_sync(0xffffffffu, bidx, o);
        if (ob < best || (ob == best && oi < bidx)) { best = ob; bidx = oi; }
    }
    if (lane == 0) {
        float cx = pcs[bidx*3+0], cy = pcs[bidx*3+1], cz = pcs[bidx*3+2];
        float dx = jx - cx, dy = jy - cy, dz = jz - cz;
        float* o = att + ((size_t)hand * M1 * Jx + (size_t)bl * Jx + w) * 3;
        o[0] = expf(-50.f * dx*dx);
        o[1] = expf(-50.f * dy*dy);
        o[2] = expf(-50.f * dz*dz);
    }
}

// ---------------- concat assembly -> packed hi/lo words ----------------
__device__ __forceinline__ float cat_elem(int c, int bl, int b, int hand,
                                          const float* xh, const float* jh,
                                          const float* mc, const float* pcn,
                                          const float* att) {
    if (c < 99)        return xh[(size_t)bl * HAND + c];
    else if (c < 162)  return jh[(size_t)bl * 63 + (c - 99)];
    else if (c < 1186) return mc[(size_t)b * Nx + (c - 162)];
    else if (c < 2210) return pcn[(size_t)bl * Nx + (c - 1186)];
    else if (c < CATD) return att[(size_t)hand * M1 * 63 + (size_t)bl * 63 + (c - 2210)];
    return 0.f;
}
__global__ void buildcat_kernel(const float* __restrict__ xl, const float* __restrict__ xr,
                                const float* __restrict__ jl, const float* __restrict__ jr,
                                const float* __restrict__ mc, const float* __restrict__ pcn,
                                const float* __restrict__ att,
                                uint32_t* __restrict__ catH, uint32_t* __restrict__ catL) {
    int bl = blockIdx.x, hand = blockIdx.y;
    int b = bl / Lx;
    size_t rowo = ((size_t)hand * M1 + bl) * KWFC;
    const float* xh = hand ? xr : xl;
    const float* jh = hand ? jr : jl;
    for (int cw = threadIdx.x; cw < KWFC; cw += blockDim.x) {
        float e = cat_elem(2*cw,     bl, b, hand, xh, jh, mc, pcn, att);
        float o = cat_elem(2*cw + 1, bl, b, hand, xh, jh, mc, pcn, att);
        uint32_t hw, lw;
        split_pair(e, o, hw, lw);
        catH[rowo + cw] = hw;
        catL[rowo + cw] = lw;
    }
}

// ---------------- bf16x3 tgemm: template NI (n-frags/warp), ldmatrix, K-split ----------------
// Block tile 128 x (NI*16). 8 warps 4m x 2n, warp tile 32 x (NI*8).
#define AST 20
#define BSTW 20
#define TASZ (128*AST)
#define TG_SMEM_NI(NI) ((4*TASZ + 4*((NI)*16)*BSTW) * 4)

template<int NI>
__global__ void __launch_bounds__(256, 2)
tgemm(const uint32_t* __restrict__ Ahw, const uint32_t* __restrict__ Alw, int Kw,
      const uint32_t* __restrict__ B1h, const uint32_t* __restrict__ B1l, const float* __restrict__ bias1,
      const uint32_t* __restrict__ B2h, const uint32_t* __restrict__ B2l, const float* __restrict__ bias2,
      float* __restrict__ C, uint32_t* __restrict__ CPh, uint32_t* __restrict__ CPl,
      int N, int flags, int rowsplit, int ksplit, size_t cstride) {
    constexpr int TBN  = NI * 16;
    constexpr int TBSZ = TBN * BSTW;
    constexpr int NP   = NI / 2;          // B ldsm frags (16-wide) per warp
    constexpr int BL   = TBN / 64;        // B staging uint4 per thread per array

    extern __shared__ uint32_t smw[];
    uint32_t* Ah = smw;
    uint32_t* Al = Ah + 2*TASZ;
    uint32_t* Bh = Al + 2*TASZ;
    uint32_t* Bl = Bh + 2*TBSZ;

    int tid = threadIdx.x;
    int row0 = blockIdx.y * 128, col0 = blockIdx.x * TBN;
    const uint32_t* Bwh = (row0 >= rowsplit) ? B2h : B1h;
    const uint32_t* Bwl = (row0 >= rowsplit) ? B2l : B1l;
    const float*   bias = (row0 >= rowsplit) ? bias2 : bias1;

    int Klen = (((Kw + ksplit - 1) / ksplit) + 15) & ~15;
    int kbeg = blockIdx.z * Klen;
    int kend = min(Kw, kbeg + Klen);
    C += (size_t)blockIdx.z * cstride;
    bool dobias = (flags & 1) && (blockIdx.z == 0);
    const int ntiles = (kend - kbeg) >> 4;

    int warp = tid >> 5, lane = tid & 31;
    int wm = warp & 3, wn = warp >> 2;
    int m0 = wm * 32, n0 = wn * (NI*8);
    int g = lane >> 2, t = lane & 3;

    int q = lane >> 3, r = lane & 7;
    uint32_t aOffW[2], bOffW[NP];
    #pragma unroll
    for (int mi = 0; mi < 2; mi++)
        aOffW[mi] = (uint32_t)((m0 + mi*16 + (q & 1)*8 + r) * AST + (q >> 1)*4);
    #pragma unroll
    for (int p = 0; p < NP; p++)
        bOffW[p] = (uint32_t)((n0 + p*16 + (q >> 1)*8 + r) * BSTW + (q & 1)*4);

    float acc[2][NI][4];
    #pragma unroll
    for (int mi = 0; mi < 2; mi++)
        #pragma unroll
        for (int ni = 0; ni < NI; ni++)
            #pragma unroll
            for (int j = 0; j < 4; j++) acc[mi][ni][j] = 0.f;

    uint4 pah[2], pal[2], pbh4[BL], pbl4[BL];
    const int a_m = tid >> 2, a_wg = (tid & 3) * 4;

    auto load_tile = [&](int ti) {
        int kw0 = kbeg + ti * 16;
        #pragma unroll
        for (int i = 0; i < 2; i++) {
            size_t base = (size_t)(row0 + a_m + i*64) * Kw + kw0 + a_wg;
            pah[i] = *(const uint4*)(Ahw + base);
            pal[i] = *(const uint4*)(Alw + base);
        }
        #pragma unroll
        for (int i = 0; i < BL; i++) {
            int idx = tid + i*256;
            int n = idx % TBN, kwg = idx / TBN;
            size_t bbase = ((size_t)((kw0 >> 2) + kwg) * N + col0 + n) * 4;
            pbh4[i] = *(const uint4*)(Bwh + bbase);
            pbl4[i] = *(const uint4*)(Bwl + bbase);
        }
    };

    auto store_tile = [&](int st) {
        uint32_t* AhS = Ah + st*TASZ; uint32_t* AlS = Al + st*TASZ;
        uint32_t* BhS = Bh + st*TBSZ; uint32_t* BlS = Bl + st*TBSZ;
        #pragma unroll
        for (int i = 0; i < 2; i++) {
            int m = a_m + i*64;
            *(uint4*)(AhS + m*AST + a_wg) = pah[i];
            *(uint4*)(AlS + m*AST + a_wg) = pal[i];
        }
        #pragma unroll
        for (int i = 0; i < BL; i++) {
            int idx = tid + i*256;
            int n = idx % TBN, kwg = idx / TBN;
            *(uint4*)(BhS + n*BSTW + kwg*4) = pbh4[i];
            *(uint4*)(BlS + n*BSTW + kwg*4) = pbl4[i];
        }
    };

    load_tile(0);
    store_tile(0);
    __syncthreads();

    for (int ti = 0; ti < ntiles; ti++) {
        int st = ti & 1;
        if (ti + 1 < ntiles) load_tile(ti + 1);

        uint32_t ahAddr = smem_u32(Ah + st*TASZ);
        uint32_t alAddr = smem_u32(Al + st*TASZ);
        uint32_t bhAddr = smem_u32(Bh + st*TBSZ);
        uint32_t blAddr = smem_u32(Bl + st*TBSZ);
        #pragma unroll
        for (int ks = 0; ks < 2; ks++) {
            uint32_t kso = (uint32_t)(ks * 8 * 4);
            uint32_t ahr[2][4], alr[2][4];
            #pragma unroll
            for (int mi = 0; mi < 2; mi++) {
                ldsm_x4(ahr[mi], ahAddr + aOffW[mi]*4 + kso);
                ldsm_x4(alr[mi], alAddr + aOffW[mi]*4 + kso);
            }
            #pragma unroll
            for (int p = 0; p < NP; p++) {
                uint32_t bhf[4], blf[4];
                ldsm_x4(bhf, bhAddr + bOffW[p]*4 + kso);
                ldsm_x4(blf, blAddr + bOffW[p]*4 + kso);
                #pragma unroll
                for (int half = 0; half < 2; half++) {
                    int ni = p*2 + half;
                    uint32_t bhr[2] = {bhf[half*2], bhf[half*2+1]};
                    uint32_t blr[2] = {blf[half*2], blf[half*2+1]};
                    #pragma unroll
                    for (int mi = 0; mi < 2; mi++) {
                        mma_bf16(acc[mi][ni], ahr[mi], bhr);
                        mma_bf16(acc[mi][ni], alr[mi], bhr);
                        mma_bf16(acc[mi][ni], ahr[mi], blr);
                    }
                }
            }
        }
        if (ti + 1 < ntiles) store_tile((ti + 1) & 1);
        __syncthreads();
    }

    int Nw = N >> 1;
    #pragma unroll
    for (int mi = 0; mi < 2; mi++) {
        int rr = row0 + m0 + mi*16 + g;
        #pragma unroll
        for (int ni = 0; ni < NI; ni++) {
            int c = col0 + n0 + ni*8 + 2*t;
            float v0 = acc[mi][ni][0], v1 = acc[mi][ni][1];
            float v2 = acc[mi][ni][2], v3 = acc[mi][ni][3];
            if (dobias) {
                float b0v = bias[c], b1v = bias[c+1];
                v0 += b0v; v1 += b1v; v2 += b0v; v3 += b1v;
            }
            if (flags & 2) {
                v0 = fmaxf(v0, 0.f); v1 = fmaxf(v1, 0.f);
                v2 = fmaxf(v2, 0.f); v3 = fmaxf(v3, 0.f);
            }
            if (flags & 4) {
                uint32_t hw, lw;
                split_pair(v0, v1, hw, lw);
                CPh[(size_t)rr*Nw + (c >> 1)] = hw;
                CPl[(size_t)rr*Nw + (c >> 1)] = lw;
                split_pair(v2, v3, hw, lw);
                CPh[(size_t)(rr+8)*Nw + (c >> 1)] = hw;
                CPl[(size_t)(rr+8)*Nw + (c >> 1)] = lw;
            } else {
                C[(size_t)rr*N + c]       = v0;
                C[(size_t)rr*N + c + 1]   = v1;
                C[(size_t)(rr+8)*N + c]   = v2;
                C[(size_t)(rr+8)*N + c+1] = v3;
            }
        }
    }
}

// ---------------- interleave (sum 2 fc slices) + PE table -> fp32 x + packed ----------------
__global__ void interleave_pe(const float* __restrict__ fl, const float* __restrict__ fr,
                              int poff, const float* __restrict__ pe,
                              float* __restrict__ x,
                              uint32_t* __restrict__ xH, uint32_t* __restrict__ xL) {
    int idx = blockIdx.x * blockDim.x + threadIdx.x;
    if (idx >= M2*KWH) return;
    int wi = idx & (KWH - 1);
    int srow = idx >> 8;
    int s = srow & (SEQ - 1);
    int b = srow >> 7;
    int l = s >> 1, h = s & 1;
    const float* src = h ? fr : fl;
    size_t base = ((size_t)(b*Lx + l)) * HIDD + wi*2;
    float2 pe2 = *(const float2*)(pe + (size_t)s*HIDD + wi*2);
    float v0 = src[base]     + src[base + poff]     + pe2.x;
    float v1 = src[base + 1] + src[base + poff + 1] + pe2.y;
    x[(size_t)srow*HIDD + wi*2]     = v0;
    x[(size_t)srow*HIDD + wi*2 + 1] = v1;
    uint32_t hw, lw;
    split_pair(v0, v1, hw, lw);
    xH[idx] = hw;
    xL[idx] = lw;
}

// ---------------- per-(b,h) attention, 256 threads (split-d) -> packed ----------------
#define ATTN_SMEM ((2*SEQ*DHD + 2*SEQ*129) * 4)
__global__ void attn_kernel(const float* __restrict__ qkv,
                            uint32_t* __restrict__ aoH, uint32_t* __restrict__ aoL) {
    extern __shared__ float sm[];
    float* Ks  = sm;
    float* Vs  = sm + SEQ*DHD;
    float* Sp0 = sm + 2*SEQ*DHD;
    float* Sp1 = Sp0 + SEQ*129;
    int b = blockIdx.x >> 3, h = blockIdx.x & 7;
    int tid = threadIdx.x;
    int qi = tid & 127, half = tid >> 7;
    for (int w4 = tid; w4 < (SEQ*DHD)/4; w4 += 256) {
        int s = w4 >> 4, d4 = (w4 & 15) * 4;
        size_t base = ((size_t)(b*SEQ + s)) * 1536 + h*64 + d4;
        *(float4*)(Ks + w4*4) = *(const float4*)(qkv + base + 512);
        *(float4*)(Vs + w4*4) = *(const float4*)(qkv + base + 1024);
    }
    float4 q4[8];
    {
        const float4* qp = (const float4*)(qkv + ((size_t)(b*SEQ + qi)) * 1536 + h*64 + half*32);
        #pragma unroll
        for (int d = 0; d < 8; d++) q4[d] = qp[d];
    }
    __syncthreads();
    float* sp = (half ? Sp1 : Sp0) + qi*129;
    for (int k = 0; k < SEQ; k++) {
        const float4* K4 = (const float4*)(Ks + k*64 + half*32);
        float s = 0.f;
        #pragma unroll
        for (int d = 0; d < 8; d++) {
            float4 kv = K4[d];
            s += q4[d].x*kv.x + q4[d].y*kv.y + q4[d].z*kv.z + q4[d].w*kv.w;
        }
        sp[k] = s;
    }
    __syncthreads();
    if (half == 0) {
        float* s0 = Sp0 + qi*129;
        float* s1 = Sp1 + qi*129;
        float m = -3.4e38f;
        for (int k = 0; k < SEQ; k++) {
            float s = (s0[k] + s1[k]) * 0.125f;
            s0[k] = s;
            m = fmaxf(m, s);
        }
        float sum = 0.f;
        for (int k = 0; k < SEQ; k++) {
            float e = expf(s0[k] - m);
            s0[k] = e; sum += e;
        }
        float inv = 1.f / sum;
        for (int k = 0; k < SEQ; k++) s0[k] *= inv;
    }
    __syncthreads();
    const float* prob = Sp0 + qi*129;
    float4 a4[8] = {};
    for (int k = 0; k < SEQ; k++) {
        float p = prob[k];
        const float4* V4 = (const float4*)(Vs + k*64 + half*32);
        #pragma unroll
        for (int j = 0; j < 8; j++) {
            float4 v = V4[j];
            a4[j].x += p*v.x; a4[j].y += p*v.y;
            a4[j].z += p*v.z; a4[j].w += p*v.w;
        }
    }
    size_t obase = (size_t)(b*SEQ + qi) * KWH + h*32 + half*16;
    #pragma unroll
    for (int j = 0; j < 8; j++) {
        uint32_t hw, lw;
        split_pair(a4[j].x, a4[j].y, hw, lw);
        aoH[obase + j*2]     = hw;
        aoL[obase + j*2]     = lw;
        split_pair(a4[j].z, a4[j].w, hw, lw);
        aoH[obase + j*2 + 1] = hw;
        aoL[obase + j*2 + 1] = lw;
    }
}

// ---------------- residual + 2-slice partial + LN -> fp32 + packed ----------------
__global__ void addln_kernel(const float* __restrict__ a, const float* __restrict__ r,
                             const float* __restrict__ r2,
                             const float* __restrict__ g, const float* __restrict__ be,
                             float* __restrict__ out,
                             uint32_t* __restrict__ outH, uint32_t* __restrict__ outL) {
    int row = blockIdx.x;
    int t = threadIdx.x;
    const float* pa  = a  + (size_t)row * HIDD;
    const float* pr  = r  + (size_t)row * HIDD;
    const float* pr2 = r2 + (size_t)row * HIDD;
    float4 a4 = *(const float4*)(pa + 4*t);
    float4 r4 = *(const float4*)(pr + 4*t);
    float4 s4 = *(const float4*)(pr2 + 4*t);
    float v[4] = {a4.x + r4.x + s4.x, a4.y + r4.y + s4.y,
                  a4.z + r4.z + s4.z, a4.w + r4.w + s4.w};
    float s = v[0] + v[1] + v[2] + v[3];
    __shared__ float sh[4];
    for (int o = 16; o; o >>= 1) s += __shfl_down_sync(0xffffffffu, s, o);
    int lane = t & 31, w = t >> 5;
    if (lane == 0) sh[w] = s;
    __syncthreads();
    float mu = (sh[0] + sh[1] + sh[2] + sh[3]) * (1.f / HIDD);
    float qv = 0.f;
    #pragma unroll
    for (int i = 0; i < 4; i++) { float d = v[i] - mu; qv += d*d; }
    __syncthreads();
    for (int o = 16; o; o >>= 1) qv += __shfl_down_sync(0xffffffffu, qv, o);
    if (lane == 0) sh[w] = qv;
    __syncthreads();
    float var = (sh[0] + sh[1] + sh[2] + sh[3]) * (1.f / HIDD);
    float inv = rsqrtf(var + 1e-5f);
    float o0 = (v[0] - mu)*inv*g[4*t+0] + be[4*t+0];
    float o1 = (v[1] - mu)*inv*g[4*t+1] + be[4*t+1];
    float o2 = (v[2] - mu)*inv*g[4*t+2] + be[4*t+2];
    float o3 = (v[3] - mu)*inv*g[4*t+3] + be[4*t+3];
    *(float4*)(out + (size_t)row * HIDD + 4*t) = make_float4(o0, o1, o2, o3);
    uint32_t hw, lw;
    split_pair(o0, o1, hw, lw);
    outH[(size_t)row * KWH + 2*t]     = hw;
    outL[(size_t)row * KWH + 2*t]     = lw;
    split_pair(o2, o3, hw, lw);
    outH[(size_t)row * KWH + 2*t + 1] = hw;
    outL[(size_t)row * KWH + 2*t + 1] = lw;
}

// ---------------- deinterleave even/odd rows -> packed ----------------
__global__ void deinterleave_packed(const float* __restrict__ x,
                                    uint32_t* __restrict__ dH, uint32_t* __restrict__ dL) {
    int idx = blockIdx.x * blockDim.x + threadIdx.x;
    if (idx >= M2*KWH) return;
    int wi = idx & (KWH - 1);
    int prow = idx >> 8;
    int hand = prow >> 10;
    int m = prow & 1023;
    int b = m >> 6, l = m & 63;
    size_t xbase = ((size_t)(b*SEQ + 2*l + hand)) * HIDD + wi*2;
    uint32_t hw, lw;
    split_pair(x[xbase], x[xbase + 1], hw, lw);
    dH[idx] = hw;
    dL[idx] = lw;
}

// ---------------- output-head finish: sum 4 K-slices + bias ----------------
__global__ void head_finish(const float* __restrict__ cpad, size_t cstride,
                            const float* __restrict__ bl, const float* __restrict__ br,
                            float* __restrict__ out) {
    int m = blockIdx.x;
    int c = threadIdx.x;
    if (c >= HAND) return;
    float v = cpad[(size_t)m*128 + c]
            + cpad[cstride     + (size_t)m*128 + c]
            + cpad[cstride*2   + (size_t)m*128 + c]
            + cpad[cstride*3   + (size_t)m*128 + c];
    int hand = m >> 10, r = m & 1023;
    v += hand ? br[c] : bl[c];
    out[((size_t)hand*M1 + r)*HAND + c] = v;
}

// ---------------- launch ----------------
extern "C" void kernel_launch(void* const* d_in, const int* in_sizes, int n_in,
                              void* d_out, int out_size) {
    const float* x_lhand     = (const float*)d_in[0];
    const float* x_rhand     = (const float*)d_in[1];
    const float* j_lhand     = (const float*)d_in[2];
    const float* j_rhand     = (const float*)d_in[3];
    const float* m_contact   = (const float*)d_in[4];
    const float* x_obj       = (const float*)d_in[5];
    const float* point_cloud = (const float*)d_in[6];
    const float* fc_lw  = (const float*)d_in[7];
    const float* fc_lb  = (const float*)d_in[8];
    const float* fc_rw  = (const float*)d_in[9];
    const float* fc_rb  = (const float*)d_in[10];
    const float* out_lw = (const float*)d_in[11];
    const float* out_lb = (const float*)d_in[12];
    const float* out_rw = (const float*)d_in[13];
    const float* out_rb = (const float*)d_in[14];
    const float* Wqkv   = (const float*)d_in[15];
    const float* bqkv   = (const float*)d_in[16];
    const float* Wo     = (const float*)d_in[17];
    const float* bo     = (const float*)d_in[18];
    const float* W1     = (const float*)d_in[19];
    const float* b1f    = (const float*)d_in[20];
    const float* W2     = (const float*)d_in[21];
    const float* b2f    = (const float*)d_in[22];
    const float* ln1_g  = (const float*)d_in[23];
    const float* ln1_b  = (const float*)d_in[24];
    const float* ln2_g  = (const float*)d_in[25];
    const float* ln2_b  = (const float*)d_in[26];
    float* out = (float*)d_out;

    float* base = nullptr;
    cudaGetSymbolAddress((void**)&base, g_scratch);
    float*    pct  = base + OFF_PCT;
    float*    pcn  = base + OFF_PCN;
    float*    att  = base + OFF_ATT;
    uint32_t* catH = (uint32_t*)(base + OFF_CATH);
    uint32_t* catL = (uint32_t*)(base + OFF_CATL);
    float*    fcb  = base + OFF_FC;
    float*    x    = base + OFF_X;
    uint32_t* xH   = (uint32_t*)(base + OFF_XH);
    uint32_t* xL   = (uint32_t*)(base + OFF_XL);
    float*    h    = base + OFF_H;
    uint32_t* hH   = (uint32_t*)(base + OFF_HH);
    uint32_t* hL   = (uint32_t*)(base + OFF_HL);
    float*    qkv  = base + OFF_QKV;
    uint32_t* aoH  = (uint32_t*)(base + OFF_AOH);
    uint32_t* aoL  = (uint32_t*)(base + OFF_AOL);
    uint32_t* ffH  = (uint32_t*)(base + OFF_FFH);
    uint32_t* ffL  = (uint32_t*)(base + OFF_FFL);
    float*    tmp  = base + OFF_TMP;
    uint32_t* fcWh = (uint32_t*)(base + OFF_FCWH);
    uint32_t* fcWl = (uint32_t*)(base + OFF_FCWL);
    uint32_t* qWh  = (uint32_t*)(base + OFF_QWH);
    uint32_t* qWl  = (uint32_t*)(base + OFF_QWL);
    uint32_t* oWh  = (uint32_t*)(base + OFF_OWH);
    uint32_t* oWl  = (uint32_t*)(base + OFF_OWL);
    uint32_t* w1h  = (uint32_t*)(base + OFF_W1H);
    uint32_t* w1l  = (uint32_t*)(base + OFF_W1L);
    uint32_t* w2h  = (uint32_t*)(base + OFF_W2H);
    uint32_t* w2l  = (uint32_t*)(base + OFF_W2L);
    uint32_t* owh  = (uint32_t*)(base + OFF_OUTWH);
    uint32_t* owl  = (uint32_t*)(base + OFF_OUTWL);
    float*    pe   = base + OFF_PE;

    cudaFuncSetAttribute(attn_kernel, cudaFuncAttributeMaxDynamicSharedMemorySize, ATTN_SMEM);
    cudaFuncSetAttribute(tgemm<4>, cudaFuncAttributeMaxDynamicSharedMemorySize, TG_SMEM_NI(4));
    cudaFuncSetAttribute(tgemm<8>, cudaFuncAttributeMaxDynamicSharedMemorySize, TG_SMEM_NI(8));

    const size_t FCST  = (size_t)2*M1*HIDD;
    const size_t TMPST = (size_t)M2*HIDD;
    const size_t HDST  = (size_t)M2*128;

    // ---- weight pre-split (group layout) + PE table ----
    split_w<<<dim3(2, KWFC/4, 1), 256>>>(fc_lw, fcWh, fcWl, CATD, HIDD, HIDD, 0, 0);
    split_w<<<dim3(2, KWFC/4, 1), 256>>>(fc_rw, fcWh + (size_t)KWFC*HIDD, fcWl + (size_t)KWFC*HIDD,
                                         CATD, HIDD, HIDD, 0, 0);
    split_w<<<dim3(6, KWH/4, NLAYERS), 256>>>(Wqkv, qWh, qWl, HIDD, 3*HIDD, 3*HIDD,
                                              (size_t)HIDD*3*HIDD, (size_t)KWH*3*HIDD);
    split_w<<<dim3(2, KWH/4, NLAYERS), 256>>>(Wo, oWh, oWl, HIDD, HIDD, HIDD,
                                              (size_t)HIDD*HIDD, (size_t)KWH*HIDD);
    split_w<<<dim3(8, KWH/4, NLAYERS), 256>>>(W1, w1h, w1l, HIDD, 4*HIDD, 4*HIDD,
                                              (size_t)HIDD*4*HIDD, (size_t)KWH*4*HIDD);
    split_w<<<dim3(2, KWF/4, NLAYERS), 256>>>(W2, w2h, w2l, 4*HIDD, HIDD, HIDD,
                                              (size_t)4*HIDD*HIDD, (size_t)KWF*HIDD);
    split_w<<<dim3(1, KWH/4, 1), 128>>>(out_lw, owh, owl, HIDD, HAND, 128, 0, 0);
    split_w<<<dim3(1, KWH/4, 1), 128>>>(out_rw, owh + (size_t)KWH*128, owl + (size_t)KWH*128,
                                        HIDD, HAND, 128, 0, 0);
    pe_table<<<(SEQ*HIDD + 255)/256, 256>>>(pe);

    // ---- geometry + concat ----
    transform_kernel<<<M1, 256>>>(x_obj, point_cloud, pct, pcn);
    attmap_kernel<<<dim3(M1, 2), Jx*32>>>(j_lhand, j_rhand, pct, att);
    buildcat_kernel<<<dim3(M1, 2), 256>>>(x_lhand, x_rhand, j_lhand, j_rhand,
                                          m_contact, pcn, att, catH, catL);

    // ---- fc projection ----
    tgemm<4><<<dim3(8, 16, 2), 256, TG_SMEM_NI(4)>>>(catH, catL, KWFC,
        fcWh, fcWl, fc_lb, fcWh + (size_t)KWFC*HIDD, fcWl + (size_t)KWFC*HIDD, fc_rb,
        fcb, nullptr, nullptr, HIDD, 1, M1, 2, FCST);
    interleave_pe<<<(M2*KWH + 255)/256, 256>>>(fcb, fcb + M1*HIDD, (int)FCST, pe, x, xH, xL);

    for (int l = 0; l < NLAYERS; l++) {
        uint32_t* lqh = qWh + (size_t)l*KWH*3*HIDD;
        uint32_t* lql = qWl + (size_t)l*KWH*3*HIDD;
        const float* bq = bqkv + (size_t)l*3*HIDD;
        tgemm<8><<<dim3(12, 16, 1), 256, TG_SMEM_NI(8)>>>(xH, xL, KWH,
            lqh, lql, bq, lqh, lql, bq, qkv, nullptr, nullptr, 3*HIDD, 1, M2, 1, 0);
        attn_kernel<<<Bx*NHEADS, 256, ATTN_SMEM>>>(qkv, aoH, aoL);
        uint32_t* loh = oWh + (size_t)l*KWH*HIDD;
        uint32_t* lol = oWl + (size_t)l*KWH*HIDD;
        const float* bob = bo + (size_t)l*HIDD;
        tgemm<4><<<dim3(8, 16, 2), 256, TG_SMEM_NI(4)>>>(aoH, aoL, KWH,
            loh, lol, bob, loh, lol, bob, tmp, nullptr, nullptr, HIDD, 1, M2, 2, TMPST);
        addln_kernel<<<M2, 128>>>(x, tmp, tmp + TMPST,
                                  ln1_g + (size_t)l*HIDD, ln1_b + (size_t)l*HIDD, h, hH, hL);
        uint32_t* l1h = w1h + (size_t)l*KWH*4*HIDD;
        uint32_t* l1l = w1l + (size_t)l*KWH*4*HIDD;
        const float* b1 = b1f + (size_t)l*4*HIDD;
        tgemm<8><<<dim3(16, 16, 1), 256, TG_SMEM_NI(8)>>>(hH, hL, KWH,
            l1h, l1l, b1, l1h, l1l, b1, nullptr, ffH, ffL, 4*HIDD, 1 | 2 | 4, M2, 1, 0);
        uint32_t* l2h = w2h + (size_t)l*KWF*HIDD;
        uint32_t* l2l = w2l + (size_t)l*KWF*HIDD;
        const float* b2 = b2f + (size_t)l*HIDD;
        tgemm<4><<<dim3(8, 16, 2), 256, TG_SMEM_NI(4)>>>(ffH, ffL, KWF,
            l2h, l2l, b2, l2h, l2l, b2, tmp, nullptr, nullptr, HIDD, 1, M2, 2, TMPST);
        addln_kernel<<<M2, 128>>>(h, tmp, tmp + TMPST,
                                  ln2_g + (size_t)l*HIDD, ln2_b + (size_t)l*HIDD, x, xH, xL);
    }

    // ---- output heads ----
    deinterleave_packed<<<(M2*KWH + 255)/256, 256>>>(x, hH, hL);
    tgemm<4><<<dim3(2, 16, 4), 256, TG_SMEM_NI(4)>>>(hH, hL, KWH,
        owh, owl, nullptr, owh + (size_t)KWH*128, owl + (size_t)KWH*128, nullptr,
        tmp, nullptr, nullptr, 128, 0, M1, 4, HDST);
    head_finish<<<M2, 128>>>(tmp, HDST, out_lb, out_rb, out);
}

// round 17
// speedup vs baseline: 1.0333x; 1.0333x over previous
#include <cuda_runtime.h>
#include <cuda_bf16.h>
#include <math.h>
#include <stdint.h>

// ---------------- problem constants ----------------
#define Bx      16
#define Lx      64
#define Nx      1024
#define HAND    99
#define Jx      21
#define HIDD    512
#define NLAYERS 4
#define NHEADS  8
#define DHD     64
#define CATD    2273
#define SEQ     128
#define M1      (Bx*Lx)      // 1024
#define M2      (Bx*SEQ)     // 2048
#define KWFC    1152         // padded word-K for fc
#define KWH     256          // HIDD/2
#define KWF     1024         // 4*HIDD/2

// ---------------- scratch arena (words = 4B each) ----------------
#define OFF_PCT   0
#define SZ_PCT    (M1*Nx*3)
#define OFF_PCN   (OFF_PCT + SZ_PCT)
#define SZ_PCN    (M1*Nx)
#define OFF_ATT   (OFF_PCN + SZ_PCN)
#define SZ_ATT    (2*M1*Jx*3)
#define OFF_CATH  (OFF_ATT + SZ_ATT)
#define SZ_CATH   (2*M1*KWFC)
#define OFF_CATL  (OFF_CATH + SZ_CATH)
#define SZ_CATL   SZ_CATH
#define OFF_FC    (OFF_CATL + SZ_CATL)
#define SZ_FC     (2 * 2*M1*HIDD)
#define OFF_X     (OFF_FC + SZ_FC)
#define SZ_X      (M2*HIDD)
#define OFF_XH    (OFF_X + SZ_X)
#define SZ_XH     (M2*KWH)
#define OFF_XL    (OFF_XH + SZ_XH)
#define SZ_XL     SZ_XH
#define OFF_H     (OFF_XL + SZ_XL)
#define SZ_H      (M2*HIDD)
#define OFF_HH    (OFF_H + SZ_H)
#define SZ_HH     (M2*KWH)
#define OFF_HL    (OFF_HH + SZ_HH)
#define SZ_HL     SZ_HH
#define OFF_QKV   (OFF_HL + SZ_HL)
#define SZ_QKV    (M2*3*HIDD)
#define OFF_AOH   (OFF_QKV + SZ_QKV)
#define SZ_AOH    (M2*KWH)
#define OFF_AOL   (OFF_AOH + SZ_AOH)
#define SZ_AOL    SZ_AOH
#define OFF_FFH   (OFF_AOL + SZ_AOL)
#define SZ_FFH    (M2*KWF)
#define OFF_FFL   (OFF_FFH + SZ_FFH)
#define SZ_FFL    SZ_FFH
#define OFF_TMP   (OFF_FFL + SZ_FFL)
#define SZ_TMP    (2 * M2*HIDD)
// packed weights (group layout: word idx = (kwg*Npad + n)*4 + j)
#define OFF_FCWH  (OFF_TMP + SZ_TMP)
#define SZ_FCWH   (2*KWFC*HIDD)
#define OFF_FCWL  (OFF_FCWH + SZ_FCWH)
#define SZ_FCWL   SZ_FCWH
#define OFF_QWH   (OFF_FCWL + SZ_FCWL)
#define SZ_QWH    (NLAYERS*KWH*3*HIDD)
#define OFF_QWL   (OFF_QWH + SZ_QWH)
#define SZ_QWL    SZ_QWH
#define OFF_OWH   (OFF_QWL + SZ_QWL)
#define SZ_OWH    (NLAYERS*KWH*HIDD)
#define OFF_OWL   (OFF_OWH + SZ_OWH)
#define SZ_OWL    SZ_OWH
#define OFF_W1H   (OFF_OWL + SZ_OWL)
#define SZ_W1H    (NLAYERS*KWH*4*HIDD)
#define OFF_W1L   (OFF_W1H + SZ_W1H)
#define SZ_W1L    SZ_W1H
#define OFF_W2H   (OFF_W1L + SZ_W1L)
#define SZ_W2H    (NLAYERS*KWF*HIDD)
#define OFF_W2L   (OFF_W2H + SZ_W2H)
#define SZ_W2L    SZ_W2H
#define OFF_OUTWH (OFF_W2L + SZ_W2L)
#define SZ_OUTWH  (2*KWH*128)
#define OFF_OUTWL (OFF_OUTWH + SZ_OUTWH)
#define SZ_OUTWL  SZ_OUTWH
#define OFF_PE    (OFF_OUTWL + SZ_OUTWL)
#define SZ_PE     (SEQ*HIDD)
#define SCRATCH_TOTAL (OFF_PE + SZ_PE)

__device__ float g_scratch[SCRATCH_TOTAL];

// ---------------- bf16 helpers ----------------
__device__ __forceinline__ uint32_t pack_bf16(float e, float o) {
    uint32_t r;
    asm("cvt.rn.bf16x2.f32 %0, %1, %2;" : "=r"(r) : "f"(o), "f"(e));
    return r;
}
__device__ __forceinline__ float2 unpack_bf16(uint32_t w) {
    float2 f;
    f.x = __uint_as_float(w << 16);
    f.y = __uint_as_float(w & 0xffff0000u);
    return f;
}
__device__ __forceinline__ void split_pair(float e, float o, uint32_t& hw, uint32_t& lw) {
    hw = pack_bf16(e, o);
    float2 hf = unpack_bf16(hw);
    lw = pack_bf16(e - hf.x, o - hf.y);
}
__device__ __forceinline__ void mma_bf16(float* c, const uint32_t* a, const uint32_t* b) {
    asm("mma.sync.aligned.m16n8k16.row.col.f32.bf16.bf16.f32 "
        "{%0,%1,%2,%3}, {%4,%5,%6,%7}, {%8,%9}, {%0,%1,%2,%3};\n"
        : "+f"(c[0]), "+f"(c[1]), "+f"(c[2]), "+f"(c[3])
        : "r"(a[0]), "r"(a[1]), "r"(a[2]), "r"(a[3]), "r"(b[0]), "r"(b[1]));
}
__device__ __forceinline__ void ldsm_x4(uint32_t* r, uint32_t addr) {
    asm volatile("ldmatrix.sync.aligned.m8n8.x4.shared.b16 {%0,%1,%2,%3}, [%4];"
        : "=r"(r[0]), "=r"(r[1]), "=r"(r[2]), "=r"(r[3]) : "r"(addr));
}
__device__ __forceinline__ uint32_t smem_u32(const void* p) {
    uint32_t a;
    asm("{ .reg .u64 t; cvta.to.shared.u64 t, %1; cvt.u32.u64 %0, t; }" : "=r"(a) : "l"(p));
    return a;
}

// ---------------- weight pre-split: W[K][Nsrc] -> group layout [kwg][Npad][4] ----------------
__global__ void split_w(const float* __restrict__ W, uint32_t* __restrict__ Wh,
                        uint32_t* __restrict__ Wl, int K, int Nsrc, int Npad,
                        size_t wstride, size_t pstride) {
    int n = blockIdx.x * blockDim.x + threadIdx.x;
    if (n >= Npad) return;
    int kwg = blockIdx.y;
    int l   = blockIdx.z;
    const float* Ws = W + (size_t)l * wstride;
    uint32_t hw[4], lw[4];
    #pragma unroll
    for (int j = 0; j < 4; j++) {
        int kw = kwg*4 + j;
        float e = 0.f, o = 0.f;
        if (n < Nsrc) {
            if (2*kw     < K) e = Ws[(size_t)(2*kw)*Nsrc + n];
            if (2*kw + 1 < K) o = Ws[(size_t)(2*kw+1)*Nsrc + n];
        }
        split_pair(e, o, hw[j], lw[j]);
    }
    size_t base = (size_t)l*pstride + ((size_t)kwg*Npad + n)*4;
    *(uint4*)(Wh + base) = make_uint4(hw[0], hw[1], hw[2], hw[3]);
    *(uint4*)(Wl + base) = make_uint4(lw[0], lw[1], lw[2], lw[3]);
}

// ---------------- PE table ----------------
__global__ void pe_table(float* __restrict__ pe) {
    int idx = blockIdx.x * blockDim.x + threadIdx.x;
    if (idx >= SEQ*HIDD) return;
    int d = idx & (HIDD - 1);
    int s = idx >> 9;
    int l = s >> 1, h = s & 1;
    float div = expf((float)(d & ~1) * (-9.2103403719761836f / 512.f));
    float pl = (d & 1) ? cosf((float)l * div) : sinf((float)l * div);
    float pa = (d & 1) ? cosf((float)h * div) : sinf((float)h * div);
    pe[idx] = pl + pa;
}

// ---------------- rot6d + pc transform + norm ----------------
__global__ void transform_kernel(const float* __restrict__ x_obj,
                                 const float* __restrict__ pc,
                                 float* __restrict__ pct,
                                 float* __restrict__ pcn) {
    int bl = blockIdx.x;
    int b  = bl / Lx;
    const float* xo = x_obj + (size_t)bl * 10;
    float tx = xo[0], ty = xo[1], tz = xo[2];
    float a1x = xo[3], a1y = xo[4], a1z = xo[5];
    float a2x = xo[6], a2y = xo[7], a2z = xo[8];
    float n1 = sqrtf(a1x*a1x + a1y*a1y + a1z*a1z);
    float b1x = a1x/n1, b1y = a1y/n1, b1z = a1z/n1;
    float dd  = b1x*a2x + b1y*a2y + b1z*a2z;
    float b2x = a2x - dd*b1x, b2y = a2y - dd*b1y, b2z = a2z - dd*b1z;
    float n2 = sqrtf(b2x*b2x + b2y*b2y + b2z*b2z);
    b2x /= n2; b2y /= n2; b2z /= n2;
    float b3x = b1y*b2z - b1z*b2y;
    float b3y = b1z*b2x - b1x*b2z;
    float b3z = b1x*b2y - b1y*b2x;
    const float* pcb = pc + (size_t)b * Nx * 3;
    for (int n = threadIdx.x; n < Nx; n += blockDim.x) {
        float px = pcb[n*3+0], py = pcb[n*3+1], pz = pcb[n*3+2];
        float ox = b1x*px + b2x*py + b3x*pz + tx;
        float oy = b1y*px + b2y*py + b3y*pz + ty;
        float oz = b1z*px + b2z*py + b3z*pz + tz;
        float* o = pct + ((size_t)bl * Nx + n) * 3;
        o[0] = ox; o[1] = oy; o[2] = oz;
        pcn[(size_t)bl * Nx + n] = sqrtf(ox*ox + oy*oy + oz*oz);
    }
}

// ---------------- nearest-point attention map ----------------
__global__ void attmap_kernel(const float* __restrict__ jl,
                              const float* __restrict__ jr,
                              const float* __restrict__ pct,
                              float* __restrict__ att) {
    __shared__ float pcs[Nx*3];
    int bl = blockIdx.x, hand = blockIdx.y;
    const float* src = pct + (size_t)bl * Nx * 3;
    for (int i = threadIdx.x; i < Nx*3; i += blockDim.x) pcs[i] = src[i];
    __syncthreads();
    int w = threadIdx.x >> 5, lane = threadIdx.x & 31;
    if (w >= Jx) return;
    const float* jp = (hand ? jr : jl) + ((size_t)bl * Jx + w) * 3;
    float jx = jp[0], jy = jp[1], jz = jp[2];
    float jj = jx*jx + jy*jy + jz*jz;
    float best = 3.4e38f; int bidx = Nx;
    for (int n = lane; n < Nx; n += 32) {
        float px = pcs[n*3+0], py = pcs[n*3+1], pz = pcs[n*3+2];
        float pp = px*px + py*py + pz*pz;
        float d2 = jj + pp - 2.f*(jx*px + jy*py + jz*pz);
        if (d2 < best || (d2 == best && n < bidx)) { best = d2; bidx = n; }
    }
    for (int o = 16; o; o >>= 1) {
        float ob = __shfl_down_sync(0xffffffffu, best, o);
        int   oi = __shfl_down_sync(0xffffffffu, bidx, o);
        if (ob < best || (ob == best && oi < bidx)) { best = ob; bidx = oi; }
    }
    if (lane == 0) {
        float cx = pcs[bidx*3+0], cy = pcs[bidx*3+1], cz = pcs[bidx*3+2];
        float dx = jx - cx, dy = jy - cy, dz = jz - cz;
        float* o = att + ((size_t)hand * M1 * Jx + (size_t)bl * Jx + w) * 3;
        o[0] = expf(-50.f * dx*dx);
        o[1] = expf(-50.f * dy*dy);
        o[2] = expf(-50.f * dz*dz);
    }
}

// ---------------- concat assembly -> packed hi/lo words ----------------
__device__ __forceinline__ float cat_elem(int c, int bl, int b, int hand,
                                          const float* xh, const float* jh,
                                          const float* mc, const float* pcn,
                                          const float* att) {
    if (c < 99)        return xh[(size_t)bl * HAND + c];
    else if (c < 162)  return jh[(size_t)bl * 63 + (c - 99)];
    else if (c < 1186) return mc[(size_t)b * Nx + (c - 162)];
    else if (c < 2210) return pcn[(size_t)bl * Nx + (c - 1186)];
    else if (c < CATD) return att[(size_t)hand * M1 * 63 + (size_t)bl * 63 + (c - 2210)];
    return 0.f;
}
__global__ void buildcat_kernel(const float* __restrict__ xl, const float* __restrict__ xr,
                                const float* __restrict__ jl, const float* __restrict__ jr,
                                const float* __restrict__ mc, const float* __restrict__ pcn,
                                const float* __restrict__ att,
                                uint32_t* __restrict__ catH, uint32_t* __restrict__ catL) {
    int bl = blockIdx.x, hand = blockIdx.y;
    int b = bl / Lx;
    size_t rowo = ((size_t)hand * M1 + bl) * KWFC;
    const float* xh = hand ? xr : xl;
    const float* jh = hand ? jr : jl;
    for (int cw = threadIdx.x; cw < KWFC; cw += blockDim.x) {
        float e = cat_elem(2*cw,     bl, b, hand, xh, jh, mc, pcn, att);
        float o = cat_elem(2*cw + 1, bl, b, hand, xh, jh, mc, pcn, att);
        uint32_t hw, lw;
        split_pair(e, o, hw, lw);
        catH[rowo + cw] = hw;
        catL[rowo + cw] = lw;
    }
}

// ---------------- bf16x3 tgemm: packed operands, ldmatrix, K-split (R13/R15 proven core) ----------------
#define AST 20
#define BSTW 20
#define TASZ (128*AST)
#define TBSZ (64*BSTW)
#define TG_SMEM ((4*TASZ + 4*TBSZ) * 4)

__global__ void __launch_bounds__(256, 2)
tgemm(const uint32_t* __restrict__ Ahw, const uint32_t* __restrict__ Alw, int Kw,
      const uint32_t* __restrict__ B1h, const uint32_t* __restrict__ B1l, const float* __restrict__ bias1,
      const uint32_t* __restrict__ B2h, const uint32_t* __restrict__ B2l, const float* __restrict__ bias2,
      float* __restrict__ C, uint32_t* __restrict__ CPh, uint32_t* __restrict__ CPl,
      int N, int flags, int rowsplit, int ksplit, size_t cstride) {
    extern __shared__ uint32_t smw[];
    uint32_t* Ah = smw;
    uint32_t* Al = Ah + 2*TASZ;
    uint32_t* Bh = Al + 2*TASZ;
    uint32_t* Bl = Bh + 2*TBSZ;

    int tid = threadIdx.x;
    int row0 = blockIdx.y * 128, col0 = blockIdx.x * 64;
    const uint32_t* Bwh = (row0 >= rowsplit) ? B2h : B1h;
    const uint32_t* Bwl = (row0 >= rowsplit) ? B2l : B1l;
    const float*   bias = (row0 >= rowsplit) ? bias2 : bias1;

    int Klen = (((Kw + ksplit - 1) / ksplit) + 15) & ~15;
    int kbeg = blockIdx.z * Klen;
    int kend = min(Kw, kbeg + Klen);
    C += (size_t)blockIdx.z * cstride;
    bool dobias = (flags & 1) && (blockIdx.z == 0);
    const int ntiles = (kend - kbeg) >> 4;

    int warp = tid >> 5, lane = tid & 31;
    int wm = warp & 3, wn = warp >> 2;
    int m0 = wm * 32, n0 = wn * 32;
    int g = lane >> 2, t = lane & 3;

    int q = lane >> 3, r = lane & 7;
    uint32_t aOffW[2], bOffW[2];
    #pragma unroll
    for (int mi = 0; mi < 2; mi++)
        aOffW[mi] = (uint32_t)((m0 + mi*16 + (q & 1)*8 + r) * AST + (q >> 1)*4);
    #pragma unroll
    for (int p = 0; p < 2; p++)
        bOffW[p] = (uint32_t)((n0 + p*16 + (q >> 1)*8 + r) * BSTW + (q & 1)*4);

    float acc[2][4][4];
    #pragma unroll
    for (int mi = 0; mi < 2; mi++)
        #pragma unroll
        for (int ni = 0; ni < 4; ni++)
            #pragma unroll
            for (int j = 0; j < 4; j++) acc[mi][ni][j] = 0.f;

    uint4 pah[2], pal[2], pbh4, pbl4;
    const int a_m = tid >> 2, a_wg = (tid & 3) * 4;
    const int b_n = tid & 63, b_wg = tid >> 6;

    auto load_tile = [&](int ti) {
        int kw0 = kbeg + ti * 16;
        #pragma unroll
        for (int i = 0; i < 2; i++) {
            size_t base = (size_t)(row0 + a_m + i*64) * Kw + kw0 + a_wg;
            pah[i] = *(const uint4*)(Ahw + base);
            pal[i] = *(const uint4*)(Alw + base);
        }
        size_t bbase = ((size_t)((kw0 >> 2) + b_wg) * N + col0 + b_n) * 4;
        pbh4 = *(const uint4*)(Bwh + bbase);
        pbl4 = *(const uint4*)(Bwl + bbase);
    };

    auto store_tile = [&](int st) {
        uint32_t* AhS = Ah + st*TASZ; uint32_t* AlS = Al + st*TASZ;
        uint32_t* BhS = Bh + st*TBSZ; uint32_t* BlS = Bl + st*TBSZ;
        #pragma unroll
        for (int i = 0; i < 2; i++) {
            int m = a_m + i*64;
            *(uint4*)(AhS + m*AST + a_wg) = pah[i];
            *(uint4*)(AlS + m*AST + a_wg) = pal[i];
        }
        *(uint4*)(BhS + b_n*BSTW + b_wg*4) = pbh4;
        *(uint4*)(BlS + b_n*BSTW + b_wg*4) = pbl4;
    };

    load_tile(0);
    store_tile(0);
    __syncthreads();

    for (int ti = 0; ti < ntiles; ti++) {
        int st = ti & 1;
        if (ti + 1 < ntiles) load_tile(ti + 1);

        uint32_t ahAddr = smem_u32(Ah + st*TASZ);
        uint32_t alAddr = smem_u32(Al + st*TASZ);
        uint32_t bhAddr = smem_u32(Bh + st*TBSZ);
        uint32_t blAddr = smem_u32(Bl + st*TBSZ);
        #pragma unroll
        for (int ks = 0; ks < 2; ks++) {
            uint32_t kso = (uint32_t)(ks * 8 * 4);
            uint32_t ahr[2][4], alr[2][4];
            #pragma unroll
            for (int mi = 0; mi < 2; mi++) {
                ldsm_x4(ahr[mi], ahAddr + aOffW[mi]*4 + kso);
                ldsm_x4(alr[mi], alAddr + aOffW[mi]*4 + kso);
            }
            uint32_t bhf[2][4], blf[2][4];
            #pragma unroll
            for (int p = 0; p < 2; p++) {
                ldsm_x4(bhf[p], bhAddr + bOffW[p]*4 + kso);
                ldsm_x4(blf[p], blAddr + bOffW[p]*4 + kso);
            }
            #pragma unroll
            for (int ni = 0; ni < 4; ni++) {
                int p = ni >> 1, o = (ni & 1) * 2;
                uint32_t bhr[2] = {bhf[p][o], bhf[p][o+1]};
                uint32_t blr[2] = {blf[p][o], blf[p][o+1]};
                #pragma unroll
                for (int mi = 0; mi < 2; mi++) {
                    mma_bf16(acc[mi][ni], ahr[mi], bhr);
                    mma_bf16(acc[mi][ni], alr[mi], bhr);
                    mma_bf16(acc[mi][ni], ahr[mi], blr);
                }
            }
        }
        if (ti + 1 < ntiles) store_tile((ti + 1) & 1);
        __syncthreads();
    }

    int Nw = N >> 1;
    #pragma unroll
    for (int mi = 0; mi < 2; mi++) {
        int rr = row0 + m0 + mi*16 + g;
        #pragma unroll
        for (int ni = 0; ni < 4; ni++) {
            int c = col0 + n0 + ni*8 + 2*t;
            float v0 = acc[mi][ni][0], v1 = acc[mi][ni][1];
            float v2 = acc[mi][ni][2], v3 = acc[mi][ni][3];
            if (dobias) {
                float b0v = bias[c], b1v = bias[c+1];
                v0 += b0v; v1 += b1v; v2 += b0v; v3 += b1v;
            }
            if (flags & 2) {
                v0 = fmaxf(v0, 0.f); v1 = fmaxf(v1, 0.f);
                v2 = fmaxf(v2, 0.f); v3 = fmaxf(v3, 0.f);
            }
            if (flags & 4) {
                uint32_t hw, lw;
                split_pair(v0, v1, hw, lw);
                CPh[(size_t)rr*Nw + (c >> 1)] = hw;
                CPl[(size_t)rr*Nw + (c >> 1)] = lw;
                split_pair(v2, v3, hw, lw);
                CPh[(size_t)(rr+8)*Nw + (c >> 1)] = hw;
                CPl[(size_t)(rr+8)*Nw + (c >> 1)] = lw;
            } else {
                C[(size_t)rr*N + c]       = v0;
                C[(size_t)rr*N + c + 1]   = v1;
                C[(size_t)(rr+8)*N + c]   = v2;
                C[(size_t)(rr+8)*N + c+1] = v3;
            }
        }
    }
}

// ---------------- interleave (sum 2 fc slices) + PE table -> fp32 x + packed ----------------
__global__ void interleave_pe(const float* __restrict__ fl, const float* __restrict__ fr,
                              int poff, const float* __restrict__ pe,
                              float* __restrict__ x,
                              uint32_t* __restrict__ xH, uint32_t* __restrict__ xL) {
    int idx = blockIdx.x * blockDim.x + threadIdx.x;
    if (idx >= M2*KWH) return;
    int wi = idx & (KWH - 1);
    int srow = idx >> 8;
    int s = srow & (SEQ - 1);
    int b = srow >> 7;
    int l = s >> 1, h = s & 1;
    const float* src = h ? fr : fl;
    size_t base = ((size_t)(b*Lx + l)) * HIDD + wi*2;
    float2 pe2 = *(const float2*)(pe + (size_t)s*HIDD + wi*2);
    float v0 = src[base]     + src[base + poff]     + pe2.x;
    float v1 = src[base + 1] + src[base + poff + 1] + pe2.y;
    x[(size_t)srow*HIDD + wi*2]     = v0;
    x[(size_t)srow*HIDD + wi*2 + 1] = v1;
    uint32_t hw, lw;
    split_pair(v0, v1, hw, lw);
    xH[idx] = hw;
    xL[idx] = lw;
}

// ---------------- per-(b,h) attention, 256 threads (split-d) -> packed ----------------
#define ATTN_SMEM ((2*SEQ*DHD + 2*SEQ*129) * 4)
__global__ void attn_kernel(const float* __restrict__ qkv,
                            uint32_t* __restrict__ aoH, uint32_t* __restrict__ aoL) {
    extern __shared__ float sm[];
    float* Ks  = sm;
    float* Vs  = sm + SEQ*DHD;
    float* Sp0 = sm + 2*SEQ*DHD;
    float* Sp1 = Sp0 + SEQ*129;
    int b = blockIdx.x >> 3, h = blockIdx.x & 7;
    int tid = threadIdx.x;
    int qi = tid & 127, half = tid >> 7;
    for (int w4 = tid; w4 < (SEQ*DHD)/4; w4 += 256) {
        int s = w4 >> 4, d4 = (w4 & 15) * 4;
        size_t base = ((size_t)(b*SEQ + s)) * 1536 + h*64 + d4;
        *(float4*)(Ks + w4*4) = *(const float4*)(qkv + base + 512);
        *(float4*)(Vs + w4*4) = *(const float4*)(qkv + base + 1024);
    }
    float4 q4[8];
    {
        const float4* qp = (const float4*)(qkv + ((size_t)(b*SEQ + qi)) * 1536 + h*64 + half*32);
        #pragma unroll
        for (int d = 0; d < 8; d++) q4[d] = qp[d];
    }
    __syncthreads();
    float* sp = (half ? Sp1 : Sp0) + qi*129;
    for (int k = 0; k < SEQ; k++) {
        const float4* K4 = (const float4*)(Ks + k*64 + half*32);
        float s = 0.f;
        #pragma unroll
        for (int d = 0; d < 8; d++) {
            float4 kv = K4[d];
            s += q4[d].x*kv.x + q4[d].y*kv.y + q4[d].z*kv.z + q4[d].w*kv.w;
        }
        sp[k] = s;
    }
    __syncthreads();
    if (half == 0) {
        float* s0 = Sp0 + qi*129;
        float* s1 = Sp1 + qi*129;
        float m = -3.4e38f;
        for (int k = 0; k < SEQ; k++) {
            float s = (s0[k] + s1[k]) * 0.125f;
            s0[k] = s;
            m = fmaxf(m, s);
        }
        float sum = 0.f;
        for (int k = 0; k < SEQ; k++) {
            float e = expf(s0[k] - m);
            s0[k] = e; sum += e;
        }
        float inv = 1.f / sum;
        for (int k = 0; k < SEQ; k++) s0[k] *= inv;
    }
    __syncthreads();
    const float* prob = Sp0 + qi*129;
    float4 a4[8] = {};
    for (int k = 0; k < SEQ; k++) {
        float p = prob[k];
        const float4* V4 = (const float4*)(Vs + k*64 + half*32);
        #pragma unroll
        for (int j = 0; j < 8; j++) {
            float4 v = V4[j];
            a4[j].x += p*v.x; a4[j].y += p*v.y;
            a4[j].z += p*v.z; a4[j].w += p*v.w;
        }
    }
    size_t obase = (size_t)(b*SEQ + qi) * KWH + h*32 + half*16;
    #pragma unroll
    for (int j = 0; j < 8; j++) {
        uint32_t hw, lw;
        split_pair(a4[j].x, a4[j].y, hw, lw);
        aoH[obase + j*2]     = hw;
        aoL[obase + j*2]     = lw;
        split_pair(a4[j].z, a4[j].w, hw, lw);
        aoH[obase + j*2 + 1] = hw;
        aoL[obase + j*2 + 1] = lw;
    }
}

// ---------------- residual + 2-slice partial + LN -> fp32 + packed (optional row-permute) ----------------
__global__ void addln_kernel(const float* __restrict__ a, const float* __restrict__ r,
                             const float* __restrict__ r2,
                             const float* __restrict__ g, const float* __restrict__ be,
                             float* __restrict__ out,
                             uint32_t* __restrict__ outH, uint32_t* __restrict__ outL,
                             int permute) {
    int row = blockIdx.x;
    int t = threadIdx.x;
    const float* pa  = a  + (size_t)row * HIDD;
    const float* pr  = r  + (size_t)row * HIDD;
    const float* pr2 = r2 + (size_t)row * HIDD;
    float4 a4 = *(const float4*)(pa + 4*t);
    float4 r4 = *(const float4*)(pr + 4*t);
    float4 s4 = *(const float4*)(pr2 + 4*t);
    float v[4] = {a4.x + r4.x + s4.x, a4.y + r4.y + s4.y,
                  a4.z + r4.z + s4.z, a4.w + r4.w + s4.w};
    float s = v[0] + v[1] + v[2] + v[3];
    __shared__ float sh[4];
    for (int o = 16; o; o >>= 1) s += __shfl_down_sync(0xffffffffu, s, o);
    int lane = t & 31, w = t >> 5;
    if (lane == 0) sh[w] = s;
    __syncthreads();
    float mu = (sh[0] + sh[1] + sh[2] + sh[3]) * (1.f / HIDD);
    float qv = 0.f;
    #pragma unroll
    for (int i = 0; i < 4; i++) { float d = v[i] - mu; qv += d*d; }
    __syncthreads();
    for (int o = 16; o; o >>= 1) qv += __shfl_down_sync(0xffffffffu, qv, o);
    if (lane == 0) sh[w] = qv;
    __syncthreads();
    float var = (sh[0] + sh[1] + sh[2] + sh[3]) * (1.f / HIDD);
    float inv = rsqrtf(var + 1e-5f);
    float o0 = (v[0] - mu)*inv*g[4*t+0] + be[4*t+0];
    float o1 = (v[1] - mu)*inv*g[4*t+1] + be[4*t+1];
    float o2 = (v[2] - mu)*inv*g[4*t+2] + be[4*t+2];
    float o3 = (v[3] - mu)*inv*g[4*t+3] + be[4*t+3];
    int prow = row;
    if (permute) {
        // row = b*128 + 2*l + hand  ->  prow = hand*1024 + b*64 + l
        int sN = row & (SEQ - 1), bN = row >> 7;
        int hand = sN & 1, lN = sN >> 1;
        prow = hand * M1 + bN * Lx + lN;
    } else {
        *(float4*)(out + (size_t)row * HIDD + 4*t) = make_float4(o0, o1, o2, o3);
    }
    uint32_t hw, lw;
    split_pair(o0, o1, hw, lw);
    outH[(size_t)prow * KWH + 2*t]     = hw;
    outL[(size_t)prow * KWH + 2*t]     = lw;
    split_pair(o2, o3, hw, lw);
    outH[(size_t)prow * KWH + 2*t + 1] = hw;
    outL[(size_t)prow * KWH + 2*t + 1] = lw;
}

// ---------------- output-head finish: sum 4 K-slices + bias ----------------
__global__ void head_finish(const float* __restrict__ cpad, size_t cstride,
                            const float* __restrict__ bl, const float* __restrict__ br,
                            float* __restrict__ out) {
    int m = blockIdx.x;
    int c = threadIdx.x;
    if (c >= HAND) return;
    float v = cpad[(size_t)m*128 + c]
            + cpad[cstride     + (size_t)m*128 + c]
            + cpad[cstride*2   + (size_t)m*128 + c]
            + cpad[cstride*3   + (size_t)m*128 + c];
    int hand = m >> 10, r = m & 1023;
    v += hand ? br[c] : bl[c];
    out[((size_t)hand*M1 + r)*HAND + c] = v;
}

// ---------------- launch ----------------
extern "C" void kernel_launch(void* const* d_in, const int* in_sizes, int n_in,
                              void* d_out, int out_size) {
    const float* x_lhand     = (const float*)d_in[0];
    const float* x_rhand     = (const float*)d_in[1];
    const float* j_lhand     = (const float*)d_in[2];
    const float* j_rhand     = (const float*)d_in[3];
    const float* m_contact   = (const float*)d_in[4];
    const float* x_obj       = (const float*)d_in[5];
    const float* point_cloud = (const float*)d_in[6];
    const float* fc_lw  = (const float*)d_in[7];
    const float* fc_lb  = (const float*)d_in[8];
    const float* fc_rw  = (const float*)d_in[9];
    const float* fc_rb  = (const float*)d_in[10];
    const float* out_lw = (const float*)d_in[11];
    const float* out_lb = (const float*)d_in[12];
    const float* out_rw = (const float*)d_in[13];
    const float* out_rb = (const float*)d_in[14];
    const float* Wqkv   = (const float*)d_in[15];
    const float* bqkv   = (const float*)d_in[16];
    const float* Wo     = (const float*)d_in[17];
    const float* bo     = (const float*)d_in[18];
    const float* W1     = (const float*)d_in[19];
    const float* b1f    = (const float*)d_in[20];
    const float* W2     = (const float*)d_in[21];
    const float* b2f    = (const float*)d_in[22];
    const float* ln1_g  = (const float*)d_in[23];
    const float* ln1_b  = (const float*)d_in[24];
    const float* ln2_g  = (const float*)d_in[25];
    const float* ln2_b  = (const float*)d_in[26];
    float* out = (float*)d_out;

    float* base = nullptr;
    cudaGetSymbolAddress((void**)&base, g_scratch);
    float*    pct  = base + OFF_PCT;
    float*    pcn  = base + OFF_PCN;
    float*    att  = base + OFF_ATT;
    uint32_t* catH = (uint32_t*)(base + OFF_CATH);
    uint32_t* catL = (uint32_t*)(base + OFF_CATL);
    float*    fcb  = base + OFF_FC;
    float*    x    = base + OFF_X;
    uint32_t* xH   = (uint32_t*)(base + OFF_XH);
    uint32_t* xL   = (uint32_t*)(base + OFF_XL);
    float*    h    = base + OFF_H;
    uint32_t* hH   = (uint32_t*)(base + OFF_HH);
    uint32_t* hL   = (uint32_t*)(base + OFF_HL);
    float*    qkv  = base + OFF_QKV;
    uint32_t* aoH  = (uint32_t*)(base + OFF_AOH);
    uint32_t* aoL  = (uint32_t*)(base + OFF_AOL);
    uint32_t* ffH  = (uint32_t*)(base + OFF_FFH);
    uint32_t* ffL  = (uint32_t*)(base + OFF_FFL);
    float*    tmp  = base + OFF_TMP;
    uint32_t* fcWh = (uint32_t*)(base + OFF_FCWH);
    uint32_t* fcWl = (uint32_t*)(base + OFF_FCWL);
    uint32_t* qWh  = (uint32_t*)(base + OFF_QWH);
    uint32_t* qWl  = (uint32_t*)(base + OFF_QWL);
    uint32_t* oWh  = (uint32_t*)(base + OFF_OWH);
    uint32_t* oWl  = (uint32_t*)(base + OFF_OWL);
    uint32_t* w1h  = (uint32_t*)(base + OFF_W1H);
    uint32_t* w1l  = (uint32_t*)(base + OFF_W1L);
    uint32_t* w2h  = (uint32_t*)(base + OFF_W2H);
    uint32_t* w2l  = (uint32_t*)(base + OFF_W2L);
    uint32_t* owh  = (uint32_t*)(base + OFF_OUTWH);
    uint32_t* owl  = (uint32_t*)(base + OFF_OUTWL);
    float*    pe   = base + OFF_PE;

    cudaFuncSetAttribute(attn_kernel, cudaFuncAttributeMaxDynamicSharedMemorySize, ATTN_SMEM);
    cudaFuncSetAttribute(tgemm, cudaFuncAttributeMaxDynamicSharedMemorySize, TG_SMEM);

    const size_t FCST  = (size_t)2*M1*HIDD;
    const size_t TMPST = (size_t)M2*HIDD;
    const size_t HDST  = (size_t)M2*128;

    // ---- weight pre-split (group layout) + PE table ----
    split_w<<<dim3(2, KWFC/4, 1), 256>>>(fc_lw, fcWh, fcWl, CATD, HIDD, HIDD, 0, 0);
    split_w<<<dim3(2, KWFC/4, 1), 256>>>(fc_rw, fcWh + (size_t)KWFC*HIDD, fcWl + (size_t)KWFC*HIDD,
                                         CATD, HIDD, HIDD, 0, 0);
    split_w<<<dim3(6, KWH/4, NLAYERS), 256>>>(Wqkv, qWh, qWl, HIDD, 3*HIDD, 3*HIDD,
                                              (size_t)HIDD*3*HIDD, (size_t)KWH*3*HIDD);
    split_w<<<dim3(2, KWH/4, NLAYERS), 256>>>(Wo, oWh, oWl, HIDD, HIDD, HIDD,
                                              (size_t)HIDD*HIDD, (size_t)KWH*HIDD);
    split_w<<<dim3(8, KWH/4, NLAYERS), 256>>>(W1, w1h, w1l, HIDD, 4*HIDD, 4*HIDD,
                                              (size_t)HIDD*4*HIDD, (size_t)KWH*4*HIDD);
    split_w<<<dim3(2, KWF/4, NLAYERS), 256>>>(W2, w2h, w2l, 4*HIDD, HIDD, HIDD,
                                              (size_t)4*HIDD*HIDD, (size_t)KWF*HIDD);
    split_w<<<dim3(1, KWH/4, 1), 128>>>(out_lw, owh, owl, HIDD, HAND, 128, 0, 0);
    split_w<<<dim3(1, KWH/4, 1), 128>>>(out_rw, owh + (size_t)KWH*128, owl + (size_t)KWH*128,
                                        HIDD, HAND, 128, 0, 0);
    pe_table<<<(SEQ*HIDD + 255)/256, 256>>>(pe);

    // ---- geometry + concat ----
    transform_kernel<<<M1, 256>>>(x_obj, point_cloud, pct, pcn);
    attmap_kernel<<<dim3(M1, 2), Jx*32>>>(j_lhand, j_rhand, pct, att);
    buildcat_kernel<<<dim3(M1, 2), 256>>>(x_lhand, x_rhand, j_lhand, j_rhand,
                                          m_contact, pcn, att, catH, catL);

    // ---- fc projection ----
    tgemm<<<dim3(8, 16, 2), 256, TG_SMEM>>>(catH, catL, KWFC,
        fcWh, fcWl, fc_lb, fcWh + (size_t)KWFC*HIDD, fcWl + (size_t)KWFC*HIDD, fc_rb,
        fcb, nullptr, nullptr, HIDD, 1, M1, 2, FCST);
    interleave_pe<<<(M2*KWH + 255)/256, 256>>>(fcb, fcb + M1*HIDD, (int)FCST, pe, x, xH, xL);

    for (int l = 0; l < NLAYERS; l++) {
        uint32_t* lqh = qWh + (size_t)l*KWH*3*HIDD;
        uint32_t* lql = qWl + (size_t)l*KWH*3*HIDD;
        const float* bq = bqkv + (size_t)l*3*HIDD;
        tgemm<<<dim3(24, 16, 1), 256, TG_SMEM>>>(xH, xL, KWH,
            lqh, lql, bq, lqh, lql, bq, qkv, nullptr, nullptr, 3*HIDD, 1, M2, 1, 0);
        attn_kernel<<<Bx*NHEADS, 256, ATTN_SMEM>>>(qkv, aoH, aoL);
        uint32_t* loh = oWh + (size_t)l*KWH*HIDD;
        uint32_t* lol = oWl + (size_t)l*KWH*HIDD;
        const float* bob = bo + (size_t)l*HIDD;
        tgemm<<<dim3(8, 16, 2), 256, TG_SMEM>>>(aoH, aoL, KWH,
            loh, lol, bob, loh, lol, bob, tmp, nullptr, nullptr, HIDD, 1, M2, 2, TMPST);
        addln_kernel<<<M2, 128>>>(x, tmp, tmp + TMPST,
                                  ln1_g + (size_t)l*HIDD, ln1_b + (size_t)l*HIDD, h, hH, hL, 0);
        uint32_t* l1h = w1h + (size_t)l*KWH*4*HIDD;
        uint32_t* l1l = w1l + (size_t)l*KWH*4*HIDD;
        const float* b1 = b1f + (size_t)l*4*HIDD;
        tgemm<<<dim3(32, 16, 1), 256, TG_SMEM>>>(hH, hL, KWH,
            l1h, l1l, b1, l1h, l1l, b1, nullptr, ffH, ffL, 4*HIDD, 1 | 2 | 4, M2, 1, 0);
        uint32_t* l2h = w2h + (size_t)l*KWF*HIDD;
        uint32_t* l2l = w2l + (size_t)l*KWF*HIDD;
        const float* b2 = b2f + (size_t)l*HIDD;
        tgemm<<<dim3(8, 16, 2), 256, TG_SMEM>>>(ffH, ffL, KWF,
            l2h, l2l, b2, l2h, l2l, b2, tmp, nullptr, nullptr, HIDD, 1, M2, 2, TMPST);
        // last layer: write packed output directly in head (deinterleaved) row order
        int last = (l == NLAYERS - 1);
        addln_kernel<<<M2, 128>>>(h, tmp, tmp + TMPST,
                                  ln2_g + (size_t)l*HIDD, ln2_b + (size_t)l*HIDD,
                                  x, last ? hH : xH, last ? hL : xL, last);
    }

    // ---- output heads: single tgemm (K-split 4) + finish ----
    tgemm<<<dim3(2, 16, 4), 256, TG_SMEM>>>(hH, hL, KWH,
        owh, owl, nullptr, owh + (size_t)KWH*128, owl + (size_t)KWH*128, nullptr,
        tmp, nullptr, nullptr, 128, 0, M1, 4, HDST);
    head_finish<<<M2, 128>>>(tmp, HDST, out_lb, out_rb, out);
}